// round 3
// baseline (speedup 1.0000x reference)
#include <cuda_runtime.h>
#include <math.h>

#define N_OBS   256
#define N_Y     128
#define N_X     64
#define NITERS  150
#define EPT_STRIDE 260   // stride mod 32 = 4 -> conflict-free float4 LDS across rows

__device__ float g_epT[N_Y * N_OBS];            // ep transposed [j][t]
__device__ float g_yhat_fallback[N_OBS * N_Y];

struct SolverSmem {
    float epT[N_Y * EPT_STRIDE];                // 133120 B, shared by both scenarios
    float zA[N_Y],  zB[N_Y];
    float yhA[N_Y], yhB[N_Y];
    float wA[N_OBS], wB[N_OBS];
    float partA[N_OBS], partB[N_OBS];
    float vA[N_Y], vB[N_Y];
    float redIA[8], redWA[8], redIB[8], redWB[8];
    float cA, etaA, lamA;
    float cB, etaB, lamB;
};

// ---------------------------------------------------------------------------
// Kernel 1: Y_hat = X @ W^T + b ; epT = (Y - Y_hat)^T
// ---------------------------------------------------------------------------
__global__ void prep_kernel(const float* __restrict__ X,
                            const float* __restrict__ Y,
                            const float* __restrict__ W,
                            const float* __restrict__ b,
                            float* __restrict__ yhat_out) {
    __shared__ float Xs[N_X];
    __shared__ float Ws[N_Y * (N_X + 1)];
    const int t = blockIdx.x;
    const int i = threadIdx.x;

    if (i < N_X) Xs[i] = X[t * N_X + i];
    for (int idx = i; idx < N_Y * N_X; idx += blockDim.x) {
        int r = idx >> 6, cx = idx & 63;
        Ws[r * (N_X + 1) + cx] = W[idx];
    }
    __syncthreads();

    float acc = b[i];
#pragma unroll
    for (int x = 0; x < N_X; x++) acc += Xs[x] * Ws[i * (N_X + 1) + x];

    yhat_out[t * N_Y + i] = acc;
    g_epT[i * N_OBS + t] = Y[t * N_Y + i] - acc;
}

// ---------------------------------------------------------------------------
// Warp-local exact simplex projection of 128 values (one warp, 4 vals/lane).
// Reads v[0..127] from SMEM, writes z[j] = max(v[j] - theta, 0).
// ---------------------------------------------------------------------------
__device__ __forceinline__ void project_warp(const float* __restrict__ vv,
                                             float* __restrict__ zz) {
    const unsigned FULL = 0xffffffffu;
    const int lane = threadIdx.x & 31;

    // value index i = r*32 + lane
    float val[4];
#pragma unroll
    for (int r = 0; r < 4; r++) val[r] = vv[r * 32 + lane];

    // Bitonic ascending sort over i. Strides >=32 are register-local (same lane),
    // strides <=16 are shfl_xor.
#pragma unroll
    for (int kk = 2; kk <= 128; kk <<= 1) {
#pragma unroll
        for (int jj = kk >> 1; jj > 0; jj >>= 1) {
            if (jj >= 32) {
                const int rx = jj >> 5;   // 1 or 2
#pragma unroll
                for (int r = 0; r < 4; r++) {
                    if ((r & rx) == 0) {
                        const int r2 = r | rx;
                        const bool asc = (((r * 32) & kk) == 0);  // lane bits < bit5
                        const float a = val[r], b = val[r2];
                        const float lo = fminf(a, b), hi = fmaxf(a, b);
                        val[r]  = asc ? lo : hi;
                        val[r2] = asc ? hi : lo;
                    }
                }
            } else {
#pragma unroll
                for (int r = 0; r < 4; r++) {
                    const float pv = __shfl_xor_sync(FULL, val[r], jj);
                    const bool asc   = (((r * 32 + lane) & kk) == 0);
                    const bool lower = ((lane & jj) == 0);
                    val[r] = (lower == asc) ? fminf(val[r], pv) : fmaxf(val[r], pv);
                }
            }
        }
    }

    // Inclusive prefix sum P[i] over ascending-sorted values.
    float P[4];
    float off = 0.0f;
#pragma unroll
    for (int r = 0; r < 4; r++) {
        float x = val[r];
#pragma unroll
        for (int d = 1; d < 32; d <<= 1) {
            const float y = __shfl_up_sync(FULL, x, d);
            if (lane >= d) x += y;
        }
        P[r] = x + off;
        off += __shfl_sync(FULL, x, 31);
    }
    const float Stot = off;

    // Descending cumsum at position i (idx = 127 - i): css = Stot - P[i] + u[i].
    // cond[idx] = u_desc[idx] + (1 - css[idx]) / (idx+1) > 0, idx+1 = 128 - i.
    int rho = 0;
    float cssr[4];
#pragma unroll
    for (int r = 0; r < 4; r++) {
        const int i = r * 32 + lane;
        const float css = Stot - P[r] + val[r];
        cssr[r] = css;
        const bool cond = (val[r] + (1.0f - css) / (float)(128 - i)) > 0.0f;
        rho += __popc(__ballot_sync(FULL, cond));
    }

    // theta = (css[rho-1] - 1) / rho ; css[rho-1] lives at i = 128 - rho.
    const int it = 128 - rho;
    const int rt = it >> 5, lt = it & 31;
    const float sel = (rt == 0) ? cssr[0] : (rt == 1) ? cssr[1]
                    : (rt == 2) ? cssr[2] : cssr[3];
    const float css_t = __shfl_sync(FULL, sel, lt);
    const float theta = (css_t - 1.0f) / (float)rho;

#pragma unroll
    for (int r = 0; r < 4; r++) {
        const int j = r * 32 + lane;
        zz[j] = fmaxf(vv[j] - theta, 0.0f);
    }
}

// ---------------------------------------------------------------------------
// Kernel 2: one CTA per TWO scenarios; 150 projected-subgradient iterations.
// Thread t handles observation t for both scenarios (shared ep_r registers).
// ---------------------------------------------------------------------------
__global__ __launch_bounds__(256, 1)
void solver_kernel(const float* __restrict__ yhat_all,
                   const float* __restrict__ delta_p,
                   const float* __restrict__ gamma_p,
                   float* __restrict__ zout) {
    extern __shared__ char smem_raw[];
    SolverSmem* S = reinterpret_cast<SolverSmem*>(smem_raw);

    const int tid = threadIdx.x;
    const int sA = blockIdx.x * 2;
    const int sB = sA + 1;
    const float delta = *delta_p;
    const float gamma = *gamma_p;

    for (int idx = tid; idx < N_Y * N_OBS; idx += 256) {
        const int j = idx >> 8;
        const int t = idx & 255;
        S->epT[j * EPT_STRIDE + t] = g_epT[idx];
    }
    if (tid < N_Y) {
        S->zA[tid] = 1.0f / (float)N_Y;
        S->zB[tid] = 1.0f / (float)N_Y;
        S->yhA[tid] = yhat_all[sA * N_Y + tid];
        S->yhB[tid] = yhat_all[sB * N_Y + tid];
    }
    if (tid == 0)  { S->cA = 0.0f; S->etaA = 0.0f; S->lamA = 0.1f; }
    if (tid == 32) { S->cB = 0.0f; S->etaB = 0.0f; S->lamB = 0.1f; }
    __syncthreads();

    // Cache ep row t in registers: ep[t][j]
    float ep_r[N_Y];
#pragma unroll
    for (int j = 0; j < N_Y; j++) ep_r[j] = S->epT[j * EPT_STRIDE + tid];

    for (int k = 0; k < NITERS; k++) {
        const float lr = 0.05f / sqrtf(1.0f + (float)k);
        const float cA = S->cA, etaA = S->etaA, lamA = S->lamA;
        const float cB = S->cB, etaB = S->etaB, lamB = S->lamB;

        // ---- Phase A: r_t for both scenarios (register FMAs, z broadcast) ----
        float rA = -cA, rB = -cB;
        const float4* zA4 = reinterpret_cast<const float4*>(S->zA);
        const float4* zB4 = reinterpret_cast<const float4*>(S->zB);
#pragma unroll
        for (int q = 0; q < N_Y / 4; q++) {
            const float4 za = zA4[q];
            const float4 zb = zB4[q];
            rA += ep_r[4*q+0] * za.x; rB += ep_r[4*q+0] * zb.x;
            rA += ep_r[4*q+1] * za.y; rB += ep_r[4*q+1] * zb.y;
            rA += ep_r[4*q+2] * za.z; rB += ep_r[4*q+2] * zb.z;
            rA += ep_r[4*q+3] * za.w; rB += ep_r[4*q+3] * zb.w;
        }

        const float aA = rA * rA - etaA;
        const float aB = rB * rB - etaB;
        float IA = (aA > -lamA) ? 1.0f : ((aA < -lamA) ? 0.0f : 0.5f);
        float IB = (aB > -lamB) ? 1.0f : ((aB < -lamB) ? 0.0f : 0.5f);
        const float wAv = IA * 2.0f * rA * (1.0f / (float)N_OBS);
        const float wBv = IB * 2.0f * rB * (1.0f / (float)N_OBS);
        S->wA[tid] = wAv;
        S->wB[tid] = wBv;

        float sIA = IA, sWA = wAv, sIB = IB, sWB = wBv;
#pragma unroll
        for (int off = 16; off > 0; off >>= 1) {
            sIA += __shfl_down_sync(0xffffffffu, sIA, off);
            sWA += __shfl_down_sync(0xffffffffu, sWA, off);
            sIB += __shfl_down_sync(0xffffffffu, sIB, off);
            sWB += __shfl_down_sync(0xffffffffu, sWB, off);
        }
        if ((tid & 31) == 0) {
            const int wd = tid >> 5;
            S->redIA[wd] = sIA; S->redWA[wd] = sWA;
            S->redIB[wd] = sIB; S->redWB[wd] = sWB;
        }
        __syncthreads();   // B1: w, reductions visible

        // ---- Scalar updates (overlap with Phase B) ----
        if (tid == 0) {
            float SI = 0.0f, SW = 0.0f;
#pragma unroll
            for (int i = 0; i < 8; i++) { SI += S->redIA[i]; SW += S->redWA[i]; }
            S->cA   = cA + lr * SW;                                  // g_c = -SW
            S->etaA = etaA - lr * (1.0f - SI * (1.0f / (float)N_OBS));
            S->lamA = fmaxf(lamA - lr * (delta - 1.0f + SI * (1.0f / (float)N_OBS)), 0.0f);
        }
        if (tid == 32) {
            float SI = 0.0f, SW = 0.0f;
#pragma unroll
            for (int i = 0; i < 8; i++) { SI += S->redIB[i]; SW += S->redWB[i]; }
            S->cB   = cB + lr * SW;
            S->etaB = etaB - lr * (1.0f - SI * (1.0f / (float)N_OBS));
            S->lamB = fmaxf(lamB - lr * (delta - 1.0f + SI * (1.0f / (float)N_OBS)), 0.0f);
        }

        // ---- Phase B: g_z[j] = sum_t w_t * epT[j][t], both scenarios ----
        {
            const int j = tid & 127;
            const int tbase = (tid >> 7) << 7;   // 0 or 128
            const float4* row = reinterpret_cast<const float4*>(&S->epT[j * EPT_STRIDE + tbase]);
            const float4* a4 = reinterpret_cast<const float4*>(&S->wA[tbase]);
            const float4* b4 = reinterpret_cast<const float4*>(&S->wB[tbase]);
            float accA = 0.0f, accB = 0.0f;
#pragma unroll
            for (int q = 0; q < 32; q++) {
                const float4 e  = row[q];
                const float4 wa = a4[q];
                const float4 wb = b4[q];
                accA += e.x * wa.x + e.y * wa.y + e.z * wa.z + e.w * wa.w;
                accB += e.x * wb.x + e.y * wb.y + e.z * wb.z + e.w * wb.w;
            }
            S->partA[tid] = accA;
            S->partB[tid] = accB;
        }
        __syncthreads();   // B2

        if (tid < 128) {
            const float gz = S->partA[tid] + S->partA[tid + 128] - gamma * S->yhA[tid];
            S->vA[tid] = S->zA[tid] - lr * gz;
        } else {
            const int j2 = tid - 128;
            const float gz = S->partB[j2] + S->partB[j2 + 128] - gamma * S->yhB[j2];
            S->vB[j2] = S->zB[j2] - lr * gz;
        }
        __syncthreads();   // B3

        const int wid = tid >> 5;
        if (wid == 0)      project_warp(S->vA, S->zA);
        else if (wid == 1) project_warp(S->vB, S->zB);
        __syncthreads();   // B4
    }

    if (tid < 128) {
        zout[sA * N_Y + tid] = S->zA[tid];
    } else {
        zout[sB * N_Y + (tid - 128)] = S->zB[tid - 128];
    }
}

// ---------------------------------------------------------------------------
extern "C" void kernel_launch(void* const* d_in, const int* in_sizes, int n_in,
                              void* d_out, int out_size) {
    const float* X     = (const float*)d_in[0];
    const float* Y     = (const float*)d_in[1];
    const float* W     = (const float*)d_in[2];
    const float* b     = (const float*)d_in[3];
    const float* delta = (const float*)d_in[4];
    const float* gamma = (const float*)d_in[5];

    float* out = (float*)d_out;
    float* zout = out;
    float* yhat;
    if (out_size >= 2 * N_OBS * N_Y) {
        yhat = out + N_OBS * N_Y;
    } else {
        void* p = nullptr;
        cudaGetSymbolAddress(&p, g_yhat_fallback);
        yhat = (float*)p;
    }

    static const size_t smem_bytes = sizeof(SolverSmem);
    cudaFuncSetAttribute(solver_kernel,
                         cudaFuncAttributeMaxDynamicSharedMemorySize,
                         (int)smem_bytes);

    prep_kernel<<<N_OBS, N_Y>>>(X, Y, W, b, yhat);
    solver_kernel<<<N_OBS / 2, 256, smem_bytes>>>(yhat, delta, gamma, zout);
}

// round 4
// speedup vs baseline: 1.0251x; 1.0251x over previous
#include <cuda_runtime.h>
#include <math.h>

#define N_OBS   256
#define N_Y     128
#define N_X     64
#define NITERS  150
#define EPT_STRIDE 260   // stride mod 32 = 4 -> conflict-free float4/128b LDS across rows

__device__ float g_epT[N_Y * N_OBS];            // ep transposed [j][t]
__device__ float g_yhat_fallback[N_OBS * N_Y];

struct SolverSmem {
    float epT[N_Y * EPT_STRIDE];                // 133120 B, shared by both scenarios
    float zA[N_Y],  zB[N_Y];
    float yhA[N_Y], yhB[N_Y];
    float wA[N_OBS], wB[N_OBS];
    float partA[N_OBS], partB[N_OBS];
    float redIA[8], redWA[8], redIB[8], redWB[8];
    float cA, etaA, lamA;
    float cB, etaB, lamB;
};

// ---- packed f32x2 helpers (sm_103a) ---------------------------------------
__device__ __forceinline__ void fma2(unsigned long long& d,
                                     unsigned long long a,
                                     unsigned long long b) {
    asm("fma.rn.f32x2 %0, %1, %2, %0;" : "+l"(d) : "l"(a), "l"(b));
}
__device__ __forceinline__ unsigned long long pk2(float lo, float hi) {
    unsigned long long r;
    asm("mov.b64 %0, {%1, %2};" : "=l"(r) : "f"(lo), "f"(hi));
    return r;
}
__device__ __forceinline__ float upk_sum(unsigned long long v) {
    float lo, hi;
    asm("mov.b64 {%0, %1}, %2;" : "=f"(lo), "=f"(hi) : "l"(v));
    return lo + hi;
}

// ---------------------------------------------------------------------------
// Kernel 1: Y_hat = X @ W^T + b ; epT = (Y - Y_hat)^T
// ---------------------------------------------------------------------------
__global__ void prep_kernel(const float* __restrict__ X,
                            const float* __restrict__ Y,
                            const float* __restrict__ W,
                            const float* __restrict__ b,
                            float* __restrict__ yhat_out) {
    __shared__ float Xs[N_X];
    __shared__ float Ws[N_Y * (N_X + 1)];
    const int t = blockIdx.x;
    const int i = threadIdx.x;

    if (i < N_X) Xs[i] = X[t * N_X + i];
    for (int idx = i; idx < N_Y * N_X; idx += blockDim.x) {
        int r = idx >> 6, cx = idx & 63;
        Ws[r * (N_X + 1) + cx] = W[idx];
    }
    __syncthreads();

    float acc = b[i];
#pragma unroll
    for (int x = 0; x < N_X; x++) acc += Xs[x] * Ws[i * (N_X + 1) + x];

    yhat_out[t * N_Y + i] = acc;
    g_epT[i * N_OBS + t] = Y[t * N_Y + i] - acc;
}

// ---------------------------------------------------------------------------
// Warp-local: v = z - lr*(part[j]+part[j+128]-gamma*yh[j]); z = proj_simplex(v)
// One warp handles 128 values (4/lane). Exact sort-based projection.
// ---------------------------------------------------------------------------
__device__ __forceinline__ void project_warp(const float* __restrict__ part,
                                             const float* __restrict__ yh,
                                             float* __restrict__ zz,
                                             float lr, float gamma) {
    const unsigned FULL = 0xffffffffu;
    const int lane = threadIdx.x & 31;

    float vorig[4], val[4];
#pragma unroll
    for (int r = 0; r < 4; r++) {
        const int j = r * 32 + lane;
        const float gz = part[j] + part[j + 128] - gamma * yh[j];
        vorig[r] = zz[j] - lr * gz;
        val[r] = vorig[r];
    }

    // Bitonic ascending sort over i = r*32 + lane.
#pragma unroll
    for (int kk = 2; kk <= 128; kk <<= 1) {
#pragma unroll
        for (int jj = kk >> 1; jj > 0; jj >>= 1) {
            if (jj >= 32) {
                const int rx = jj >> 5;
#pragma unroll
                for (int r = 0; r < 4; r++) {
                    if ((r & rx) == 0) {
                        const int r2 = r | rx;
                        const bool asc = (((r * 32) & kk) == 0);
                        const float a = val[r], b = val[r2];
                        const float lo = fminf(a, b), hi = fmaxf(a, b);
                        val[r]  = asc ? lo : hi;
                        val[r2] = asc ? hi : lo;
                    }
                }
            } else {
#pragma unroll
                for (int r = 0; r < 4; r++) {
                    const float pv = __shfl_xor_sync(FULL, val[r], jj);
                    const bool asc   = (((r * 32 + lane) & kk) == 0);
                    const bool lower = ((lane & jj) == 0);
                    val[r] = (lower == asc) ? fminf(val[r], pv) : fmaxf(val[r], pv);
                }
            }
        }
    }

    // 4 independent 32-lane inclusive scans (ILP), then carry combine.
    float x[4];
#pragma unroll
    for (int r = 0; r < 4; r++) x[r] = val[r];
#pragma unroll
    for (int d = 1; d < 32; d <<= 1) {
#pragma unroll
        for (int r = 0; r < 4; r++) {
            const float y = __shfl_up_sync(FULL, x[r], d);
            if (lane >= d) x[r] += y;
        }
    }
    float tot[4];
#pragma unroll
    for (int r = 0; r < 4; r++) tot[r] = __shfl_sync(FULL, x[r], 31);
    float off[4];
    off[0] = 0.0f;
    off[1] = tot[0];
    off[2] = tot[0] + tot[1];
    off[3] = off[2] + tot[2];
    const float Stot = off[3] + tot[3];

    float P[4];
#pragma unroll
    for (int r = 0; r < 4; r++) P[r] = x[r] + off[r];

    // Descending cumsum at sorted position i: css = Stot - P[i] + u[i].
    int rho = 0;
    float cssr[4];
#pragma unroll
    for (int r = 0; r < 4; r++) {
        const int i = r * 32 + lane;
        const float css = Stot - P[r] + val[r];
        cssr[r] = css;
        const bool cond = (val[r] + (1.0f - css) / (float)(128 - i)) > 0.0f;
        rho += __popc(__ballot_sync(FULL, cond));
    }

    const int it = 128 - rho;          // sorted index holding css[rho-1]
    const int rt = it >> 5, lt = it & 31;
    const float sel = (rt == 0) ? cssr[0] : (rt == 1) ? cssr[1]
                    : (rt == 2) ? cssr[2] : cssr[3];
    const float css_t = __shfl_sync(FULL, sel, lt);
    const float theta = (css_t - 1.0f) / (float)rho;

#pragma unroll
    for (int r = 0; r < 4; r++) {
        const int j = r * 32 + lane;
        zz[j] = fmaxf(vorig[r] - theta, 0.0f);
    }
}

// ---------------------------------------------------------------------------
// Kernel 2: one CTA per TWO scenarios; 150 projected-subgradient iterations.
// ---------------------------------------------------------------------------
__global__ __launch_bounds__(256, 1)
void solver_kernel(const float* __restrict__ yhat_all,
                   const float* __restrict__ delta_p,
                   const float* __restrict__ gamma_p,
                   float* __restrict__ zout) {
    extern __shared__ char smem_raw[];
    SolverSmem* S = reinterpret_cast<SolverSmem*>(smem_raw);

    const int tid = threadIdx.x;
    const int sA = blockIdx.x * 2;
    const int sB = sA + 1;
    const float delta = *delta_p;
    const float gamma = *gamma_p;

    for (int idx = tid; idx < N_Y * N_OBS; idx += 256) {
        const int j = idx >> 8;
        const int t = idx & 255;
        S->epT[j * EPT_STRIDE + t] = g_epT[idx];
    }
    if (tid < N_Y) {
        S->zA[tid] = 1.0f / (float)N_Y;
        S->zB[tid] = 1.0f / (float)N_Y;
        S->yhA[tid] = yhat_all[sA * N_Y + tid];
        S->yhB[tid] = yhat_all[sB * N_Y + tid];
    }
    if (tid == 0)  { S->cA = 0.0f; S->etaA = 0.0f; S->lamA = 0.1f; }
    if (tid == 32) { S->cB = 0.0f; S->etaB = 0.0f; S->lamB = 0.1f; }
    __syncthreads();

    // Pack ep row t into 64 packed-f32x2 registers: ep2[q] = (ep[t][2q], ep[t][2q+1])
    unsigned long long ep2[N_Y / 2];
#pragma unroll
    for (int q = 0; q < N_Y / 2; q++)
        ep2[q] = pk2(S->epT[(2 * q) * EPT_STRIDE + tid],
                     S->epT[(2 * q + 1) * EPT_STRIDE + tid]);

    for (int k = 0; k < NITERS; k++) {
        const float lr = 0.05f / sqrtf(1.0f + (float)k);
        const float cA = S->cA, etaA = S->etaA, lamA = S->lamA;
        const float cB = S->cB, etaB = S->etaB, lamB = S->lamB;

        // ---- Phase A: r_t = ep_t . z - c for both scenarios (packed FMA) ----
        unsigned long long accA0 = 0, accA1 = 0, accB0 = 0, accB1 = 0;
        {
            const ulonglong2* zA2 = reinterpret_cast<const ulonglong2*>(S->zA);
            const ulonglong2* zB2 = reinterpret_cast<const ulonglong2*>(S->zB);
#pragma unroll
            for (int q = 0; q < N_Y / 4; q++) {
                const ulonglong2 za = zA2[q];
                const ulonglong2 zb = zB2[q];
                fma2(accA0, ep2[2 * q],     za.x);
                fma2(accA1, ep2[2 * q + 1], za.y);
                fma2(accB0, ep2[2 * q],     zb.x);
                fma2(accB1, ep2[2 * q + 1], zb.y);
            }
        }
        const float rA = upk_sum(accA0) + upk_sum(accA1) - cA;
        const float rB = upk_sum(accB0) + upk_sum(accB1) - cB;

        const float aA = rA * rA - etaA;
        const float aB = rB * rB - etaB;
        const float IA = (aA > -lamA) ? 1.0f : ((aA < -lamA) ? 0.0f : 0.5f);
        const float IB = (aB > -lamB) ? 1.0f : ((aB < -lamB) ? 0.0f : 0.5f);
        const float wAv = IA * 2.0f * rA * (1.0f / (float)N_OBS);
        const float wBv = IB * 2.0f * rB * (1.0f / (float)N_OBS);
        S->wA[tid] = wAv;
        S->wB[tid] = wBv;

        float sIA = IA, sWA = wAv, sIB = IB, sWB = wBv;
#pragma unroll
        for (int off = 16; off > 0; off >>= 1) {
            sIA += __shfl_down_sync(0xffffffffu, sIA, off);
            sWA += __shfl_down_sync(0xffffffffu, sWA, off);
            sIB += __shfl_down_sync(0xffffffffu, sIB, off);
            sWB += __shfl_down_sync(0xffffffffu, sWB, off);
        }
        if ((tid & 31) == 0) {
            const int wd = tid >> 5;
            S->redIA[wd] = sIA; S->redWA[wd] = sWA;
            S->redIB[wd] = sIB; S->redWB[wd] = sWB;
        }
        __syncthreads();   // B1: w + per-warp reductions visible

        // ---- Scalar updates (overlap with Phase B) ----
        if (tid == 0) {
            float SI = 0.0f, SW = 0.0f;
#pragma unroll
            for (int i = 0; i < 8; i++) { SI += S->redIA[i]; SW += S->redWA[i]; }
            S->cA   = cA + lr * SW;
            S->etaA = etaA - lr * (1.0f - SI * (1.0f / (float)N_OBS));
            S->lamA = fmaxf(lamA - lr * (delta - 1.0f + SI * (1.0f / (float)N_OBS)), 0.0f);
        }
        if (tid == 32) {
            float SI = 0.0f, SW = 0.0f;
#pragma unroll
            for (int i = 0; i < 8; i++) { SI += S->redIB[i]; SW += S->redWB[i]; }
            S->cB   = cB + lr * SW;
            S->etaB = etaB - lr * (1.0f - SI * (1.0f / (float)N_OBS));
            S->lamB = fmaxf(lamB - lr * (delta - 1.0f + SI * (1.0f / (float)N_OBS)), 0.0f);
        }

        // ---- Phase B: g_z[j] = sum_t w_t * epT[j][t], both scenarios, packed ----
        {
            const int j = tid & 127;
            const int tbase = (tid >> 7) << 7;   // 0 or 128
            const ulonglong2* row =
                reinterpret_cast<const ulonglong2*>(&S->epT[j * EPT_STRIDE + tbase]);
            const ulonglong2* a2 = reinterpret_cast<const ulonglong2*>(&S->wA[tbase]);
            const ulonglong2* b2 = reinterpret_cast<const ulonglong2*>(&S->wB[tbase]);
            unsigned long long pA0 = 0, pA1 = 0, pB0 = 0, pB1 = 0;
#pragma unroll
            for (int q = 0; q < 32; q++) {
                const ulonglong2 e  = row[q];
                const ulonglong2 wa = a2[q];
                const ulonglong2 wb = b2[q];
                fma2(pA0, e.x, wa.x);
                fma2(pA1, e.y, wa.y);
                fma2(pB0, e.x, wb.x);
                fma2(pB1, e.y, wb.y);
            }
            S->partA[tid] = upk_sum(pA0) + upk_sum(pA1);
            S->partB[tid] = upk_sum(pB0) + upk_sum(pB1);
        }
        __syncthreads();   // B2: part visible

        const int wid = tid >> 5;
        if (wid == 0)      project_warp(S->partA, S->yhA, S->zA, lr, gamma);
        else if (wid == 1) project_warp(S->partB, S->yhB, S->zB, lr, gamma);
        __syncthreads();   // B3: new z visible
    }

    if (tid < 128) {
        zout[sA * N_Y + tid] = S->zA[tid];
    } else {
        zout[sB * N_Y + (tid - 128)] = S->zB[tid - 128];
    }
}

// ---------------------------------------------------------------------------
extern "C" void kernel_launch(void* const* d_in, const int* in_sizes, int n_in,
                              void* d_out, int out_size) {
    const float* X     = (const float*)d_in[0];
    const float* Y     = (const float*)d_in[1];
    const float* W     = (const float*)d_in[2];
    const float* b     = (const float*)d_in[3];
    const float* delta = (const float*)d_in[4];
    const float* gamma = (const float*)d_in[5];

    float* out = (float*)d_out;
    float* zout = out;
    float* yhat;
    if (out_size >= 2 * N_OBS * N_Y) {
        yhat = out + N_OBS * N_Y;
    } else {
        void* p = nullptr;
        cudaGetSymbolAddress(&p, g_yhat_fallback);
        yhat = (float*)p;
    }

    static const size_t smem_bytes = sizeof(SolverSmem);
    cudaFuncSetAttribute(solver_kernel,
                         cudaFuncAttributeMaxDynamicSharedMemorySize,
                         (int)smem_bytes);

    prep_kernel<<<N_OBS, N_Y>>>(X, Y, W, b, yhat);
    solver_kernel<<<N_OBS / 2, 256, smem_bytes>>>(yhat, delta, gamma, zout);
}

// round 5
// speedup vs baseline: 1.0262x; 1.0011x over previous
#include <cuda_runtime.h>
#include <math.h>

#define N_OBS   256
#define N_Y     128
#define N_X     64
#define NITERS  150
#define EPT_STRIDE 260   // mod-4 stride: column LDS.32 conflict-free, rows 16B-aligned

__device__ float g_epT[N_Y * N_OBS];            // ep transposed [j][t]
__device__ float g_yhat_fallback[N_OBS * N_Y];

struct SolverSmem {
    float epT[N_Y * EPT_STRIDE];                // 133120 B
    float zA[N_Y],  zB[N_Y];
    float yhA[N_Y], yhB[N_Y];
    float wA[N_OBS], wB[N_OBS];
    float partA[N_OBS], partB[N_OBS];
    float redIA[8], redWA[8], redIB[8], redWB[8];
    float cA, etaA, lamA;
    float cB, etaB, lamB;
};

// ---- packed f32x2 helpers (sm_103a) ---------------------------------------
__device__ __forceinline__ void fma2(unsigned long long& d,
                                     unsigned long long a,
                                     unsigned long long b) {
    asm("fma.rn.f32x2 %0, %1, %2, %0;" : "+l"(d) : "l"(a), "l"(b));
}
__device__ __forceinline__ float upk_sum(unsigned long long v) {
    float lo, hi;
    asm("mov.b64 {%0, %1}, %2;" : "=f"(lo), "=f"(hi) : "l"(v));
    return lo + hi;
}

// ---------------------------------------------------------------------------
// Kernel 1: Y_hat = X @ W^T + b ; epT = (Y - Y_hat)^T
// ---------------------------------------------------------------------------
__global__ void prep_kernel(const float* __restrict__ X,
                            const float* __restrict__ Y,
                            const float* __restrict__ W,
                            const float* __restrict__ b,
                            float* __restrict__ yhat_out) {
    __shared__ float Xs[N_X];
    __shared__ float Ws[N_Y * (N_X + 1)];
    const int t = blockIdx.x;
    const int i = threadIdx.x;

    if (i < N_X) Xs[i] = X[t * N_X + i];
    for (int idx = i; idx < N_Y * N_X; idx += blockDim.x) {
        int r = idx >> 6, cx = idx & 63;
        Ws[r * (N_X + 1) + cx] = W[idx];
    }
    __syncthreads();

    float acc = b[i];
#pragma unroll
    for (int x = 0; x < N_X; x++) acc += Xs[x] * Ws[i * (N_X + 1) + x];

    yhat_out[t * N_Y + i] = acc;
    g_epT[i * N_OBS + t] = Y[t * N_Y + i] - acc;
}

// ---------------------------------------------------------------------------
// Warp-local: v = z - lr*(part[j]+part[j+128]-gamma*yh[j]); z = proj_simplex(v)
// ---------------------------------------------------------------------------
__device__ __forceinline__ void project_warp(const float* __restrict__ part,
                                             const float* __restrict__ yh,
                                             float* __restrict__ zz,
                                             float lr, float gamma) {
    const unsigned FULL = 0xffffffffu;
    const int lane = threadIdx.x & 31;

    float vorig[4], val[4];
#pragma unroll
    for (int r = 0; r < 4; r++) {
        const int j = r * 32 + lane;
        const float gz = part[j] + part[j + 128] - gamma * yh[j];
        vorig[r] = zz[j] - lr * gz;
        val[r] = vorig[r];
    }

    // Bitonic ascending sort over i = r*32 + lane.
#pragma unroll
    for (int kk = 2; kk <= 128; kk <<= 1) {
#pragma unroll
        for (int jj = kk >> 1; jj > 0; jj >>= 1) {
            if (jj >= 32) {
                const int rx = jj >> 5;
#pragma unroll
                for (int r = 0; r < 4; r++) {
                    if ((r & rx) == 0) {
                        const int r2 = r | rx;
                        const bool asc = (((r * 32) & kk) == 0);
                        const float a = val[r], b = val[r2];
                        const float lo = fminf(a, b), hi = fmaxf(a, b);
                        val[r]  = asc ? lo : hi;
                        val[r2] = asc ? hi : lo;
                    }
                }
            } else {
#pragma unroll
                for (int r = 0; r < 4; r++) {
                    const float pv = __shfl_xor_sync(FULL, val[r], jj);
                    const bool asc   = (((r * 32 + lane) & kk) == 0);
                    const bool lower = ((lane & jj) == 0);
                    val[r] = (lower == asc) ? fminf(val[r], pv) : fmaxf(val[r], pv);
                }
            }
        }
    }

    // 4 independent 32-lane inclusive scans (ILP), then carry combine.
    float x[4];
#pragma unroll
    for (int r = 0; r < 4; r++) x[r] = val[r];
#pragma unroll
    for (int d = 1; d < 32; d <<= 1) {
#pragma unroll
        for (int r = 0; r < 4; r++) {
            const float y = __shfl_up_sync(FULL, x[r], d);
            if (lane >= d) x[r] += y;
        }
    }
    float tot[4];
#pragma unroll
    for (int r = 0; r < 4; r++) tot[r] = __shfl_sync(FULL, x[r], 31);
    float off[4];
    off[0] = 0.0f;
    off[1] = tot[0];
    off[2] = tot[0] + tot[1];
    off[3] = off[2] + tot[2];
    const float Stot = off[3] + tot[3];

    float P[4];
#pragma unroll
    for (int r = 0; r < 4; r++) P[r] = x[r] + off[r];

    int rho = 0;
    float cssr[4];
#pragma unroll
    for (int r = 0; r < 4; r++) {
        const int i = r * 32 + lane;
        const float css = Stot - P[r] + val[r];
        cssr[r] = css;
        const bool cond = (val[r] + (1.0f - css) / (float)(128 - i)) > 0.0f;
        rho += __popc(__ballot_sync(FULL, cond));
    }

    const int it = 128 - rho;
    const int rt = it >> 5, lt = it & 31;
    const float sel = (rt == 0) ? cssr[0] : (rt == 1) ? cssr[1]
                    : (rt == 2) ? cssr[2] : cssr[3];
    const float css_t = __shfl_sync(FULL, sel, lt);
    const float theta = (css_t - 1.0f) / (float)rho;

#pragma unroll
    for (int r = 0; r < 4; r++) {
        const int j = r * 32 + lane;
        zz[j] = fmaxf(vorig[r] - theta, 0.0f);
    }
}

// ---------------------------------------------------------------------------
// Kernel 2: one CTA per TWO scenarios. Registers hold epT in COLUMN layout
// (thread owns output j, half of t) so Phase B needs no matrix LDS; Phase A
// reads matrix columns from SMEM (conflict-free, shared by both scenarios).
// ---------------------------------------------------------------------------
__global__ __launch_bounds__(256, 1)
void solver_kernel(const float* __restrict__ yhat_all,
                   const float* __restrict__ delta_p,
                   const float* __restrict__ gamma_p,
                   float* __restrict__ zout) {
    extern __shared__ char smem_raw[];
    SolverSmem* S = reinterpret_cast<SolverSmem*>(smem_raw);

    const int tid = threadIdx.x;
    const int sA = blockIdx.x * 2;
    const int sB = sA + 1;
    const float delta = *delta_p;
    const float gamma = *gamma_p;

    for (int idx = tid; idx < N_Y * N_OBS; idx += 256) {
        const int j = idx >> 8;
        const int t = idx & 255;
        S->epT[j * EPT_STRIDE + t] = g_epT[idx];
    }
    if (tid < N_Y) {
        S->zA[tid] = 1.0f / (float)N_Y;
        S->zB[tid] = 1.0f / (float)N_Y;
        S->yhA[tid] = yhat_all[sA * N_Y + tid];
        S->yhB[tid] = yhat_all[sB * N_Y + tid];
    }
    if (tid == 0)  { S->cA = 0.0f; S->etaA = 0.0f; S->lamA = 0.1f; }
    if (tid == 32) { S->cB = 0.0f; S->etaB = 0.0f; S->lamB = 0.1f; }
    __syncthreads();

    // Column-layout register cache: thread owns j = tid & 127, t-half = tbase.
    // ep2[q] = (epT[j][tbase+2q], epT[j][tbase+2q+1]) — contiguous, 16B-aligned.
    const int jown  = tid & 127;
    const int tbase = (tid >> 7) << 7;   // 0 or 128
    unsigned long long ep2[N_OBS / 4];   // 64 packed pairs = this thread's 128 t's
    {
        const ulonglong2* col =
            reinterpret_cast<const ulonglong2*>(&S->epT[jown * EPT_STRIDE + tbase]);
#pragma unroll
        for (int q = 0; q < 32; q++) {
            const ulonglong2 v = col[q];
            ep2[2 * q]     = v.x;
            ep2[2 * q + 1] = v.y;
        }
    }

    for (int k = 0; k < NITERS; k++) {
        const float lr = 0.05f / sqrtf(1.0f + (float)k);
        const float cA = S->cA, etaA = S->etaA, lamA = S->lamA;
        const float cB = S->cB, etaB = S->etaB, lamB = S->lamB;

        // ---- Phase A: r_t = ep_t . z - c, matrix columns from SMEM ----
        // Lane-consecutive t => conflict-free LDS.32; z float4 broadcast.
        float rA = -cA, rB = -cB;
        {
            const float4* zA4 = reinterpret_cast<const float4*>(S->zA);
            const float4* zB4 = reinterpret_cast<const float4*>(S->zB);
            const float* colbase = &S->epT[tid];
#pragma unroll
            for (int q = 0; q < N_Y / 4; q++) {
                const float4 za = zA4[q];
                const float4 zb = zB4[q];
                const float e0 = colbase[(4 * q + 0) * EPT_STRIDE];
                const float e1 = colbase[(4 * q + 1) * EPT_STRIDE];
                const float e2 = colbase[(4 * q + 2) * EPT_STRIDE];
                const float e3 = colbase[(4 * q + 3) * EPT_STRIDE];
                rA += e0 * za.x; rB += e0 * zb.x;
                rA += e1 * za.y; rB += e1 * zb.y;
                rA += e2 * za.z; rB += e2 * zb.z;
                rA += e3 * za.w; rB += e3 * zb.w;
            }
        }

        const float aA = rA * rA - etaA;
        const float aB = rB * rB - etaB;
        const float IA = (aA > -lamA) ? 1.0f : ((aA < -lamA) ? 0.0f : 0.5f);
        const float IB = (aB > -lamB) ? 1.0f : ((aB < -lamB) ? 0.0f : 0.5f);
        const float wAv = IA * 2.0f * rA * (1.0f / (float)N_OBS);
        const float wBv = IB * 2.0f * rB * (1.0f / (float)N_OBS);
        S->wA[tid] = wAv;
        S->wB[tid] = wBv;

        float sIA = IA, sWA = wAv, sIB = IB, sWB = wBv;
#pragma unroll
        for (int off = 16; off > 0; off >>= 1) {
            sIA += __shfl_down_sync(0xffffffffu, sIA, off);
            sWA += __shfl_down_sync(0xffffffffu, sWA, off);
            sIB += __shfl_down_sync(0xffffffffu, sIB, off);
            sWB += __shfl_down_sync(0xffffffffu, sWB, off);
        }
        if ((tid & 31) == 0) {
            const int wd = tid >> 5;
            S->redIA[wd] = sIA; S->redWA[wd] = sWA;
            S->redIB[wd] = sIB; S->redWB[wd] = sWB;
        }
        __syncthreads();   // B1: w + per-warp reductions visible

        // ---- Scalar updates (overlap with Phase B) ----
        if (tid == 0) {
            float SI = 0.0f, SW = 0.0f;
#pragma unroll
            for (int i = 0; i < 8; i++) { SI += S->redIA[i]; SW += S->redWA[i]; }
            S->cA   = cA + lr * SW;
            S->etaA = etaA - lr * (1.0f - SI * (1.0f / (float)N_OBS));
            S->lamA = fmaxf(lamA - lr * (delta - 1.0f + SI * (1.0f / (float)N_OBS)), 0.0f);
        }
        if (tid == 32) {
            float SI = 0.0f, SW = 0.0f;
#pragma unroll
            for (int i = 0; i < 8; i++) { SI += S->redIB[i]; SW += S->redWB[i]; }
            S->cB   = cB + lr * SW;
            S->etaB = etaB - lr * (1.0f - SI * (1.0f / (float)N_OBS));
            S->lamB = fmaxf(lamB - lr * (delta - 1.0f + SI * (1.0f / (float)N_OBS)), 0.0f);
        }

        // ---- Phase B: g_z[j] = sum_t w_t * epT[j][t] — matrix in registers,
        //      w read as broadcast ulonglong2 (all threads of a half: same addr).
        {
            const ulonglong2* wa2 = reinterpret_cast<const ulonglong2*>(&S->wA[tbase]);
            const ulonglong2* wb2 = reinterpret_cast<const ulonglong2*>(&S->wB[tbase]);
            unsigned long long pA0 = 0, pA1 = 0, pB0 = 0, pB1 = 0;
#pragma unroll
            for (int q = 0; q < 32; q++) {
                const ulonglong2 wa = wa2[q];
                const ulonglong2 wb = wb2[q];
                fma2(pA0, ep2[2 * q],     wa.x);
                fma2(pA1, ep2[2 * q + 1], wa.y);
                fma2(pB0, ep2[2 * q],     wb.x);
                fma2(pB1, ep2[2 * q + 1], wb.y);
            }
            S->partA[tid] = upk_sum(pA0) + upk_sum(pA1);
            S->partB[tid] = upk_sum(pB0) + upk_sum(pB1);
        }
        __syncthreads();   // B2: part visible

        const int wid = tid >> 5;
        if (wid == 0)      project_warp(S->partA, S->yhA, S->zA, lr, gamma);
        else if (wid == 1) project_warp(S->partB, S->yhB, S->zB, lr, gamma);
        __syncthreads();   // B3: new z visible
    }

    if (tid < 128) {
        zout[sA * N_Y + tid] = S->zA[tid];
    } else {
        zout[sB * N_Y + (tid - 128)] = S->zB[tid - 128];
    }
}

// ---------------------------------------------------------------------------
extern "C" void kernel_launch(void* const* d_in, const int* in_sizes, int n_in,
                              void* d_out, int out_size) {
    const float* X     = (const float*)d_in[0];
    const float* Y     = (const float*)d_in[1];
    const float* W     = (const float*)d_in[2];
    const float* b     = (const float*)d_in[3];
    const float* delta = (const float*)d_in[4];
    const float* gamma = (const float*)d_in[5];

    float* out = (float*)d_out;
    float* zout = out;
    float* yhat;
    if (out_size >= 2 * N_OBS * N_Y) {
        yhat = out + N_OBS * N_Y;
    } else {
        void* p = nullptr;
        cudaGetSymbolAddress(&p, g_yhat_fallback);
        yhat = (float*)p;
    }

    static const size_t smem_bytes = sizeof(SolverSmem);
    cudaFuncSetAttribute(solver_kernel,
                         cudaFuncAttributeMaxDynamicSharedMemorySize,
                         (int)smem_bytes);

    prep_kernel<<<N_OBS, N_Y>>>(X, Y, W, b, yhat);
    solver_kernel<<<N_OBS / 2, 256, smem_bytes>>>(yhat, delta, gamma, zout);
}